// round 10
// baseline (speedup 1.0000x reference)
#include <cuda_runtime.h>
#include <cuda_fp8.h>
#include <stdint.h>

#define DI __device__ __forceinline__

// ---------------- problem constants ----------------
constexpr int M_DIM = 4096;
constexpr int K_DIM = 4096;
constexpr int N_DIM = 16384;

// ---------------- GEMM tiling (R2 proven shape) ----------------
constexpr int MT = 128;          // CTA M tile
constexpr int NT = 256;          // CTA N tile
constexpr int KC = 128;          // K bytes per chunk
constexpr int STAGES = 4;
constexpr int NK = K_DIM / KC;   // 32 chunks
constexpr int NTHREADS = 512;    // 16 warps: 2(M) x 8(N), warp tile 64x32

constexpr int A_BYTES = MT * KC;                      // 16384
constexpr int B_BYTES = NT * KC;                      // 32768
constexpr int OFF_A = 0;
constexpr int OFF_B = STAGES * A_BYTES;               // 65536
constexpr int SMEM_BYTES = OFF_B + STAGES * B_BYTES;  // 196608

// ---------------- device scratch (allocation is forbidden) ----------------
__device__ unsigned char g_xq[(size_t)M_DIM * K_DIM];   // 16 MB fp8 activations
__device__ float         g_xs[M_DIM];                   // per-token scales
__device__ unsigned char g_wq[(size_t)N_DIM * K_DIM];   // 64 MB fp8 weights

// ---------------- PTX helpers (legal at plain sm_103) ----------------
DI uint32_t smem_u32(const void* p) {
    uint32_t a;
    asm("{ .reg .u64 t; cvta.to.shared.u64 t, %1; cvt.u32.u64 %0, t; }" : "=r"(a) : "l"(p));
    return a;
}
template <int N> DI void cp_wait_group() {
    asm volatile("cp.async.wait_group %0;" :: "n"(N) : "memory");
}
DI void cp_commit() { asm volatile("cp.async.commit_group;" ::: "memory"); }
DI void cp16(uint32_t dst, const void* src) {
    asm volatile("cp.async.cg.shared.global [%0], [%1], 16;" :: "r"(dst), "l"(src) : "memory");
}
DI uint32_t sw128(uint32_t off) { return off ^ ((off >> 3) & 0x70); }
DI uint8_t f2e4m3(float v) { return (uint8_t)__nv_cvt_float_to_fp8(v, __NV_SATFINITE, __NV_E4M3); }

DI void ldsm_x4(uint32_t* r, uint32_t a) {
    asm volatile("ldmatrix.sync.aligned.m8n8.x4.shared.b16 {%0,%1,%2,%3}, [%4];"
                 : "=r"(r[0]), "=r"(r[1]), "=r"(r[2]), "=r"(r[3]) : "r"(a));
}
DI void mma_fp8(float* d, const uint32_t* a, const uint32_t* b) {
    asm volatile(
        "mma.sync.aligned.m16n8k32.row.col.f32.e4m3.e4m3.f32 "
        "{%0,%1,%2,%3}, {%4,%5,%6,%7}, {%8,%9}, {%0,%1,%2,%3};"
        : "+f"(d[0]), "+f"(d[1]), "+f"(d[2]), "+f"(d[3])
        : "r"(a[0]), "r"(a[1]), "r"(a[2]), "r"(a[3]), "r"(b[0]), "r"(b[1]));
}

// ---------------- kernel 1: fused dynamic-quant(x) + repack(w) ----------------
constexpr int WBLK = (int)(((size_t)N_DIM * K_DIM / 4) / 256);   // 65536

__global__ void __launch_bounds__(256) quant_fused_kernel(
    const float* __restrict__ x, const float* __restrict__ w)
{
    if (blockIdx.x < M_DIM) {
        int row = blockIdx.x;
        const float4* xr = reinterpret_cast<const float4*>(x + (size_t)row * K_DIM);
        float4 v[4];
        float amax = 0.f;
#pragma unroll
        for (int j = 0; j < 4; j++) {
            v[j] = xr[threadIdx.x + j * 256];
            amax = fmaxf(amax, fmaxf(fmaxf(fabsf(v[j].x), fabsf(v[j].y)),
                                     fmaxf(fabsf(v[j].z), fabsf(v[j].w))));
        }
#pragma unroll
        for (int o = 16; o; o >>= 1) amax = fmaxf(amax, __shfl_xor_sync(0xFFFFFFFFu, amax, o));
        __shared__ float wmax[8];
        __shared__ float s_scale;
        if ((threadIdx.x & 31) == 0) wmax[threadIdx.x >> 5] = amax;
        __syncthreads();
        if (threadIdx.x == 0) {
            float m = wmax[0];
#pragma unroll
            for (int i = 1; i < 8; i++) m = fmaxf(m, wmax[i]);
            float sc = fmaxf(__fdiv_rn(m, 448.0f), 1e-12f);
            g_xs[row] = sc;
            s_scale = sc;
        }
        __syncthreads();
        float sc = s_scale;
        uint32_t* outp = reinterpret_cast<uint32_t*>(g_xq + (size_t)row * K_DIM);
#pragma unroll
        for (int j = 0; j < 4; j++) {
            uint32_t p = (uint32_t)f2e4m3(__fdiv_rn(v[j].x, sc))
                       | ((uint32_t)f2e4m3(__fdiv_rn(v[j].y, sc)) << 8)
                       | ((uint32_t)f2e4m3(__fdiv_rn(v[j].z, sc)) << 16)
                       | ((uint32_t)f2e4m3(__fdiv_rn(v[j].w, sc)) << 24);
            outp[threadIdx.x + j * 256] = p;
        }
    } else {
        size_t i = (size_t)(blockIdx.x - M_DIM) * 256 + threadIdx.x;   // float4 index
        float4 v = reinterpret_cast<const float4*>(w)[i];
        uint32_t p = (uint32_t)f2e4m3(v.x)
                   | ((uint32_t)f2e4m3(v.y) << 8)
                   | ((uint32_t)f2e4m3(v.z) << 16)
                   | ((uint32_t)f2e4m3(v.w) << 24);
        reinterpret_cast<uint32_t*>(g_wq)[i] = p;
    }
}

// ---------------- kernel 2: fp8 mma.sync GEMM + fused dequant/bias ----------------
// Proven R2 configuration: 16 warps (2x8), warp tile 64x32, double-buffered
// fragments, two syncs/chunk. 64 accum + 24 frag regs fits the 128-reg cap.
__global__ void __launch_bounds__(NTHREADS, 1) gemm_kernel(
    const float* __restrict__ wscale, const float* __restrict__ bias,
    float* __restrict__ out)
{
    extern __shared__ char smem[];
    uint32_t sb = smem_u32(smem);
    int tid = threadIdx.x;
    int m0 = blockIdx.x * MT;
    int n0 = blockIdx.y * NT;
    const unsigned char* gA = g_xq + (size_t)m0 * K_DIM;
    const unsigned char* gB = g_wq + (size_t)n0 * K_DIM;
    int lane = tid & 31, wid = tid >> 5;
    int wm = wid & 1;        // warp M index (0..1)
    int wn = wid >> 1;       // warp N index (0..7)

    // ---- cp.async loader: (128+256) rows x 8 cols16 / 512 thr = 6 per thread ----
    auto load_chunk = [&](int s, int kc) {
        const unsigned char* pa = gA + (size_t)kc * KC;
        const unsigned char* pb = gB + (size_t)kc * KC;
        uint32_t sa = sb + OFF_A + (uint32_t)(s * A_BYTES);
        uint32_t sbb = sb + OFF_B + (uint32_t)(s * B_BYTES);
#pragma unroll
        for (int i = 0; i < 6; i++) {
            int idx = tid + i * NTHREADS;
            bool isA = idx < 1024;
            int loc = isA ? idx : idx - 1024;
            int row = loc >> 3;
            int c = loc & 7;
            uint32_t dst = (isA ? sa : sbb) + sw128((uint32_t)(row * 128 + c * 16));
            const unsigned char* src = (isA ? pa : pb) + (size_t)row * K_DIM + c * 16;
            cp16(dst, src);
        }
        cp_commit();
    };

    // ---- ldmatrix per-lane addressing (fp8 tiles viewed as b16) ----
    // A: m16k32 fragments, 4 per ks (am = 0..3 over 64 rows)
    int rowA = wm * 64 + ((lane >> 3) & 1) * 8 + (lane & 7);
    uint32_t kA = ((uint32_t)(lane >> 4)) * 16;
    uint32_t xrA = (uint32_t)((rowA & 7) * 16);
    // B: x4 covers TWO n8 blocks (16 rows; lanes 0-15 first block, 16-31 second)
    int rowB = wn * 32 + (lane & 7) + ((lane >> 4) & 1) * 8;
    uint32_t kB = ((uint32_t)((lane >> 3) & 1)) * 16;
    uint32_t xrB = (uint32_t)((lane & 7) * 16);

    float d[4][4][4];
#pragma unroll
    for (int i = 0; i < 4; i++)
#pragma unroll
        for (int j = 0; j < 4; j++)
#pragma unroll
            for (int k = 0; k < 4; k++) d[i][j][k] = 0.f;

    // ---- prologue: stages 0..2 <- chunks 0..2 ----
#pragma unroll
    for (int i = 0; i < STAGES - 1; i++) load_chunk(i, i);

    for (int kc = 0; kc < NK; kc++) {
        int kl = kc + STAGES - 1;
        if (kl < NK) {
            load_chunk(kl & 3, kl);
            cp_wait_group<STAGES - 1>();
        } else {
            cp_wait_group<0>();
        }
        __syncthreads();                      // stage kc visible to all warps

        int s = kc & 3;
        uint32_t aBase = sb + OFF_A + (uint32_t)(s * A_BYTES) + (uint32_t)rowA * 128;
        uint32_t bBase = sb + OFF_B + (uint32_t)(s * B_BYTES) + (uint32_t)rowB * 128;

        uint32_t a[2][4];     // A fragment double buffer (parity on am)
        uint32_t b[2][8];     // B fragments for one ks (4 n8 blocks), double buffer

        uint32_t colA0 = kA ^ xrA;
        uint32_t colB0 = kB ^ xrB;
        ldsm_x4(&b[0][0], bBase + colB0);            // n8 blocks 0,1
        ldsm_x4(&b[0][4], bBase + 2048 + colB0);     // n8 blocks 2,3
        ldsm_x4(a[0], aBase + colA0);                // ks=0, am=0

#pragma unroll
        for (int ks = 0; ks < 4; ks++) {
            int cb = ks & 1;
            uint32_t colA = (kA + (uint32_t)ks * 32) ^ xrA;
#pragma unroll
            for (int am = 0; am < 4; am++) {
                int pa = am & 1;
                // prefetch next fragments under the MMAs
                if (am < 3) {
                    ldsm_x4(a[pa ^ 1], aBase + (uint32_t)((am + 1) * 2048) + colA);
                } else if (ks < 3) {
                    uint32_t colAn = (kA + (uint32_t)(ks + 1) * 32) ^ xrA;
                    uint32_t colBn = (kB + (uint32_t)(ks + 1) * 32) ^ xrB;
                    ldsm_x4(&b[cb ^ 1][0], bBase + colBn);
                    ldsm_x4(&b[cb ^ 1][4], bBase + 2048 + colBn);
                    ldsm_x4(a[pa ^ 1], aBase + colAn);
                }
                mma_fp8(d[am][0], a[pa], &b[cb][0]);
                mma_fp8(d[am][1], a[pa], &b[cb][2]);
                mma_fp8(d[am][2], a[pa], &b[cb][4]);
                mma_fp8(d[am][3], a[pa], &b[cb][6]);
            }
        }
        __syncthreads();                      // protect stage before overwrite
    }

    // ---- epilogue: fused per-token * per-channel dequant + bias ----
    int g = lane >> 2, tig = lane & 3;
#pragma unroll
    for (int am = 0; am < 4; am++) {
        int r0 = m0 + wm * 64 + am * 16 + g;
        int r1 = r0 + 8;
        float xs0 = g_xs[r0], xs1 = g_xs[r1];
        float* p0 = out + (size_t)r0 * N_DIM;
        float* p1 = out + (size_t)r1 * N_DIM;
#pragma unroll
        for (int bn = 0; bn < 4; bn++) {
            int c = n0 + wn * 32 + bn * 8 + tig * 2;
            float2 ws = *reinterpret_cast<const float2*>(wscale + c);
            float2 bb = *reinterpret_cast<const float2*>(bias + c);
            float2 o0, o1;
            o0.x = d[am][bn][0] * xs0 * ws.x + bb.x;
            o0.y = d[am][bn][1] * xs0 * ws.y + bb.y;
            o1.x = d[am][bn][2] * xs1 * ws.x + bb.x;
            o1.y = d[am][bn][3] * xs1 * ws.y + bb.y;
            *reinterpret_cast<float2*>(p0 + c) = o0;
            *reinterpret_cast<float2*>(p1 + c) = o1;
        }
    }
}

// ---------------- launch ----------------
extern "C" void kernel_launch(void* const* d_in, const int* in_sizes, int n_in,
                              void* d_out, int out_size) {
    const float* x  = (const float*)d_in[0];
    const float* w  = (const float*)d_in[1];
    const float* ws = (const float*)d_in[2];
    const float* b  = (const float*)d_in[3];
    float* out = (float*)d_out;

    quant_fused_kernel<<<M_DIM + WBLK, 256>>>(x, w);

    cudaFuncSetAttribute(gemm_kernel, cudaFuncAttributeMaxDynamicSharedMemorySize, SMEM_BYTES);
    dim3 grid(M_DIM / MT, N_DIM / NT);   // (32, 64); x-fastest => B-tile reuse in L2
    gemm_kernel<<<grid, NTHREADS, SMEM_BYTES>>>(ws, b, out);
}

// round 14
// speedup vs baseline: 1.0050x; 1.0050x over previous
#include <cuda_runtime.h>
#include <cuda_fp8.h>
#include <stdint.h>

#define DI __device__ __forceinline__

// ---------------- problem constants ----------------
constexpr int M_DIM = 4096;
constexpr int K_DIM = 4096;
constexpr int N_DIM = 16384;

// ---------------- GEMM tiling (the 521-us proven shape) ----------------
constexpr int MT = 128;          // CTA M tile
constexpr int NT = 256;          // CTA N tile
constexpr int KC = 128;          // K bytes per chunk
constexpr int STAGES = 4;
constexpr int NK = K_DIM / KC;   // 32 chunks
constexpr int NTHREADS = 512;    // 16 warps: 2(M) x 8(N), warp tile 64x32

constexpr int A_BYTES = MT * KC;                      // 16384
constexpr int B_BYTES = NT * KC;                      // 32768
constexpr int OFF_A = 1024;
constexpr int OFF_B = OFF_A + STAGES * A_BYTES;       // 66560
constexpr int SMEM_BYTES = OFF_B + STAGES * B_BYTES;  // 197632

// ---------------- device scratch (allocation is forbidden) ----------------
__device__ unsigned char g_xq[(size_t)M_DIM * K_DIM];   // 16 MB fp8 activations
__device__ float         g_xs[M_DIM];                   // per-token scales
__device__ unsigned char g_wq[(size_t)N_DIM * K_DIM];   // 64 MB fp8 weights

// ---------------- PTX helpers (legal at plain sm_103) ----------------
DI uint32_t smem_u32(const void* p) {
    uint32_t a;
    asm("{ .reg .u64 t; cvta.to.shared.u64 t, %1; cvt.u32.u64 %0, t; }" : "=r"(a) : "l"(p));
    return a;
}
template <int N> DI void cp_wait_group() {
    asm volatile("cp.async.wait_group %0;" :: "n"(N) : "memory");
}
DI void cp_commit() { asm volatile("cp.async.commit_group;" ::: "memory"); }
DI void cp16(uint32_t dst, const void* src) {
    asm volatile("cp.async.cg.shared.global [%0], [%1], 16;" :: "r"(dst), "l"(src) : "memory");
}
DI uint32_t sw128(uint32_t off) { return off ^ ((off >> 3) & 0x70); }
DI uint8_t f2e4m3(float v) { return (uint8_t)__nv_cvt_float_to_fp8(v, __NV_SATFINITE, __NV_E4M3); }

DI void ldsm_x4(uint32_t* r, uint32_t a) {
    asm volatile("ldmatrix.sync.aligned.m8n8.x4.shared.b16 {%0,%1,%2,%3}, [%4];"
                 : "=r"(r[0]), "=r"(r[1]), "=r"(r[2]), "=r"(r[3]) : "r"(a));
}
DI void ldsm_x2(uint32_t* r, uint32_t a) {
    asm volatile("ldmatrix.sync.aligned.m8n8.x2.shared.b16 {%0,%1}, [%2];"
                 : "=r"(r[0]), "=r"(r[1]) : "r"(a));
}
DI void mma_fp8(float* d, const uint32_t* a, const uint32_t* b) {
    asm volatile(
        "mma.sync.aligned.m16n8k32.row.col.f32.e4m3.e4m3.f32 "
        "{%0,%1,%2,%3}, {%4,%5,%6,%7}, {%8,%9}, {%0,%1,%2,%3};"
        : "+f"(d[0]), "+f"(d[1]), "+f"(d[2]), "+f"(d[3])
        : "r"(a[0]), "r"(a[1]), "r"(a[2]), "r"(a[3]), "r"(b[0]), "r"(b[1]));
}

// ---------------- kernel 1: fused dynamic-quant(x) + repack(w) ----------------
constexpr int WBLK = (int)(((size_t)N_DIM * K_DIM / 4) / 256);   // 65536

__global__ void __launch_bounds__(256) quant_fused_kernel(
    const float* __restrict__ x, const float* __restrict__ w)
{
    if (blockIdx.x < M_DIM) {
        int row = blockIdx.x;
        const float4* xr = reinterpret_cast<const float4*>(x + (size_t)row * K_DIM);
        float4 v[4];
        float amax = 0.f;
#pragma unroll
        for (int j = 0; j < 4; j++) {
            v[j] = xr[threadIdx.x + j * 256];
            amax = fmaxf(amax, fmaxf(fmaxf(fabsf(v[j].x), fabsf(v[j].y)),
                                     fmaxf(fabsf(v[j].z), fabsf(v[j].w))));
        }
#pragma unroll
        for (int o = 16; o; o >>= 1) amax = fmaxf(amax, __shfl_xor_sync(0xFFFFFFFFu, amax, o));
        __shared__ float wmax[8];
        __shared__ float s_scale;
        if ((threadIdx.x & 31) == 0) wmax[threadIdx.x >> 5] = amax;
        __syncthreads();
        if (threadIdx.x == 0) {
            float m = wmax[0];
#pragma unroll
            for (int i = 1; i < 8; i++) m = fmaxf(m, wmax[i]);
            float sc = fmaxf(__fdiv_rn(m, 448.0f), 1e-12f);
            g_xs[row] = sc;
            s_scale = sc;
        }
        __syncthreads();
        float sc = s_scale;
        uint32_t* outp = reinterpret_cast<uint32_t*>(g_xq + (size_t)row * K_DIM);
#pragma unroll
        for (int j = 0; j < 4; j++) {
            uint32_t p = (uint32_t)f2e4m3(__fdiv_rn(v[j].x, sc))
                       | ((uint32_t)f2e4m3(__fdiv_rn(v[j].y, sc)) << 8)
                       | ((uint32_t)f2e4m3(__fdiv_rn(v[j].z, sc)) << 16)
                       | ((uint32_t)f2e4m3(__fdiv_rn(v[j].w, sc)) << 24);
            outp[threadIdx.x + j * 256] = p;
        }
    } else {
        size_t i = (size_t)(blockIdx.x - M_DIM) * 256 + threadIdx.x;   // float4 index
        float4 v = reinterpret_cast<const float4*>(w)[i];
        uint32_t p = (uint32_t)f2e4m3(v.x)
                   | ((uint32_t)f2e4m3(v.y) << 8)
                   | ((uint32_t)f2e4m3(v.z) << 16)
                   | ((uint32_t)f2e4m3(v.w) << 24);
        reinterpret_cast<uint32_t*>(g_wq)[i] = p;
    }
}

// ---------------- kernel 2: fp8 mma.sync GEMM + fused dequant/bias ----------------
// The 521-us configuration: 16 warps (2x8), warp tile 64x32, SIMPLE inner loop
// (per-ks flat loads a[4][4] + b[4][2], then 16 MMAs) — short fragment live
// ranges; ptxas schedules this below the register cap with no spills.
__global__ void __launch_bounds__(NTHREADS, 1) gemm_kernel(
    const float* __restrict__ wscale, const float* __restrict__ bias,
    float* __restrict__ out)
{
    extern __shared__ char smem[];
    uint32_t sb = smem_u32(smem);
    int tid = threadIdx.x;
    int m0 = blockIdx.x * MT;
    int n0 = blockIdx.y * NT;
    const unsigned char* gA = g_xq + (size_t)m0 * K_DIM;
    const unsigned char* gB = g_wq + (size_t)n0 * K_DIM;
    int lane = tid & 31, wid = tid >> 5;
    int wm = wid & 1;        // warp M index (0..1)
    int wn = wid >> 1;       // warp N index (0..7)

    // ---- cp.async loader: (128+256) rows x 8 cols16 / 512 thr = 6 per thread ----
    auto load_chunk = [&](int s, int kc) {
        const unsigned char* pa = gA + (size_t)kc * KC;
        const unsigned char* pb = gB + (size_t)kc * KC;
        uint32_t sa = sb + OFF_A + (uint32_t)(s * A_BYTES);
        uint32_t sbb = sb + OFF_B + (uint32_t)(s * B_BYTES);
#pragma unroll
        for (int i = 0; i < 6; i++) {
            int idx = tid + i * NTHREADS;
            bool isA = idx < 1024;
            int loc = isA ? idx : idx - 1024;
            int row = loc >> 3;
            int c = loc & 7;
            uint32_t dst = (isA ? sa : sbb) + sw128((uint32_t)(row * 128 + c * 16));
            const unsigned char* src = (isA ? pa : pb) + (size_t)row * K_DIM + c * 16;
            cp16(dst, src);
        }
        cp_commit();
    };

    // ---- ldmatrix per-lane addressing (fp8 tiles viewed as b16) ----
    // A: m16k32 fragments, 4 per ks (am = 0..3 over 64 rows)
    int rowA = wm * 64 + ((lane >> 3) & 1) * 8 + (lane & 7);
    uint32_t kA = ((uint32_t)(lane >> 4)) * 16;
    uint32_t xrA = (uint32_t)((rowA & 7) * 16);
    // B: x2 per n8 block (lanes 0-15 provide addresses)
    int rowB = wn * 32 + (lane & 7);
    uint32_t kB = ((uint32_t)((lane >> 3) & 1)) * 16;
    uint32_t xrB = (uint32_t)((rowB & 7) * 16);

    float d[4][4][4];
#pragma unroll
    for (int i = 0; i < 4; i++)
#pragma unroll
        for (int j = 0; j < 4; j++)
#pragma unroll
            for (int k = 0; k < 4; k++) d[i][j][k] = 0.f;

    // ---- prologue: stages 0..2 <- chunks 0..2 ----
#pragma unroll
    for (int i = 0; i < STAGES - 1; i++) load_chunk(i, i);

    for (int kc = 0; kc < NK; kc++) {
        int kl = kc + STAGES - 1;
        if (kl < NK) {
            load_chunk(kl % STAGES, kl);
            cp_wait_group<STAGES - 1>();
        } else {
            cp_wait_group<0>();
        }
        __syncthreads();                      // stage kc visible to all warps

        int s = kc % STAGES;
        uint32_t aBase = sb + OFF_A + (uint32_t)(s * A_BYTES) + (uint32_t)rowA * 128;
        uint32_t bBase = sb + OFF_B + (uint32_t)(s * B_BYTES) + (uint32_t)rowB * 128;

#pragma unroll
        for (int ks = 0; ks < 4; ks++) {
            uint32_t a[4][4], b[4][2];
            uint32_t colA = (kA + (uint32_t)ks * 32) ^ xrA;
            uint32_t colB = (kB + (uint32_t)ks * 32) ^ xrB;
#pragma unroll
            for (int am = 0; am < 4; am++) ldsm_x4(a[am], aBase + (uint32_t)(am * 2048) + colA);
#pragma unroll
            for (int bn = 0; bn < 4; bn++) ldsm_x2(b[bn], bBase + (uint32_t)(bn * 1024) + colB);
#pragma unroll
            for (int am = 0; am < 4; am++)
#pragma unroll
                for (int bn = 0; bn < 4; bn++) mma_fp8(d[am][bn], a[am], b[bn]);
        }
        __syncthreads();                      // all warps done before stage reuse
    }

    // ---- epilogue: fused per-token * per-channel dequant + bias ----
    int g = lane >> 2, tig = lane & 3;
#pragma unroll
    for (int am = 0; am < 4; am++) {
        int r0 = m0 + wm * 64 + am * 16 + g;
        int r1 = r0 + 8;
        float xs0 = g_xs[r0], xs1 = g_xs[r1];
        float* p0 = out + (size_t)r0 * N_DIM;
        float* p1 = out + (size_t)r1 * N_DIM;
#pragma unroll
        for (int bn = 0; bn < 4; bn++) {
            int c = n0 + wn * 32 + bn * 8 + tig * 2;
            float2 ws = *reinterpret_cast<const float2*>(wscale + c);
            float2 bb = *reinterpret_cast<const float2*>(bias + c);
            float2 o0, o1;
            o0.x = d[am][bn][0] * xs0 * ws.x + bb.x;
            o0.y = d[am][bn][1] * xs0 * ws.y + bb.y;
            o1.x = d[am][bn][2] * xs1 * ws.x + bb.x;
            o1.y = d[am][bn][3] * xs1 * ws.y + bb.y;
            *reinterpret_cast<float2*>(p0 + c) = o0;
            *reinterpret_cast<float2*>(p1 + c) = o1;
        }
    }
}

// ---------------- launch ----------------
extern "C" void kernel_launch(void* const* d_in, const int* in_sizes, int n_in,
                              void* d_out, int out_size) {
    const float* x  = (const float*)d_in[0];
    const float* w  = (const float*)d_in[1];
    const float* ws = (const float*)d_in[2];
    const float* b  = (const float*)d_in[3];
    float* out = (float*)d_out;

    quant_fused_kernel<<<M_DIM + WBLK, 256>>>(x, w);

    cudaFuncSetAttribute(gemm_kernel, cudaFuncAttributeMaxDynamicSharedMemorySize, SMEM_BYTES);
    dim3 grid(M_DIM / MT, N_DIM / NT);   // (32, 64); x-fastest => B-tile reuse in L2
    gemm_kernel<<<grid, NTHREADS, SMEM_BYTES>>>(ws, b, out);
}

// round 15
// speedup vs baseline: 3.0040x; 2.9892x over previous
#include <cuda_runtime.h>
#include <cuda_fp8.h>
#include <stdint.h>

#define DI __device__ __forceinline__

// tcgen05 only exists on arch-specific ("a") targets. This macro is defined
// only when nvcc compiles a compute_103a/compute_100a pass.
#if defined(__CUDA_ARCH_FEAT_SM103_ALL) || defined(__CUDA_ARCH_FEAT_SM100_ALL)
#define HAS_TC 1
#else
#define HAS_TC 0
#endif

// ---------------- problem constants ----------------
constexpr int M_DIM = 4096;
constexpr int K_DIM = 4096;
constexpr int N_DIM = 16384;

// ---------------- GEMM tiling (shared by both paths) ----------------
constexpr int MT = 128;          // CTA M tile
constexpr int NT = 256;          // CTA N tile
constexpr int KC = 128;          // K bytes per chunk
constexpr int STAGES = 4;
constexpr int NK = K_DIM / KC;   // 32 chunks
constexpr int NTHREADS = 512;    // 16 warps

constexpr int A_BYTES = MT * KC;                      // 16384
constexpr int B_BYTES = NT * KC;                      // 32768
constexpr int OFF_MBAR = 16;
constexpr int OFF_A = 1024;
constexpr int OFF_B = OFF_A + STAGES * A_BYTES;
constexpr int SMEM_BYTES = OFF_B + STAGES * B_BYTES;  // 197632

// ---------------- device scratch (allocation is forbidden) ----------------
__device__ unsigned char g_xq[(size_t)M_DIM * K_DIM];   // 16 MB fp8 activations
__device__ float         g_xs[M_DIM];                   // per-token scales
__device__ unsigned char g_wq[(size_t)N_DIM * K_DIM];   // 64 MB fp8 weights

// ---------------- generic PTX helpers (sm_90-safe) ----------------
DI uint32_t smem_u32(const void* p) {
    uint32_t a;
    asm("{ .reg .u64 t; cvta.to.shared.u64 t, %1; cvt.u32.u64 %0, t; }" : "=r"(a) : "l"(p));
    return a;
}
DI void mbar_init(uint32_t a, uint32_t cnt) {
    asm volatile("mbarrier.init.shared.b64 [%0], %1;" :: "r"(a), "r"(cnt) : "memory");
}
DI void mbar_inval(uint32_t a) {
    asm volatile("mbarrier.inval.shared.b64 [%0];" :: "r"(a) : "memory");
}
DI void mbar_wait(uint32_t a, uint32_t parity) {
    asm volatile(
        "{\n\t.reg .pred P;\n\t"
        "WLOOP_%=:\n\t"
        "mbarrier.try_wait.parity.acquire.cta.shared::cta.b64 P, [%0], %1, 0x989680;\n\t"
        "@P bra.uni WDONE_%=;\n\t"
        "bra.uni WLOOP_%=;\n\t"
        "WDONE_%=:\n\t}"
        :: "r"(a), "r"(parity) : "memory");
}
template <int N> DI void cp_wait_group() {
    asm volatile("cp.async.wait_group %0;" :: "n"(N) : "memory");
}
DI void cp_commit() { asm volatile("cp.async.commit_group;" ::: "memory"); }
DI void cp16(uint32_t dst, const void* src) {
    asm volatile("cp.async.cg.shared.global [%0], [%1], 16;" :: "r"(dst), "l"(src) : "memory");
}
DI void fence_async_smem() { asm volatile("fence.proxy.async.shared::cta;" ::: "memory"); }

DI uint32_t sw128(uint32_t off) { return off ^ ((off >> 3) & 0x70); }
DI uint8_t f2e4m3(float v) { return (uint8_t)__nv_cvt_float_to_fp8(v, __NV_SATFINITE, __NV_E4M3); }

// ldmatrix (b16 view of fp8 tiles gives exactly the fp8 m16n8k32 fragments)
DI void ldsm_x4(uint32_t* r, uint32_t a) {
    asm volatile("ldmatrix.sync.aligned.m8n8.x4.shared.b16 {%0,%1,%2,%3}, [%4];"
                 : "=r"(r[0]), "=r"(r[1]), "=r"(r[2]), "=r"(r[3]) : "r"(a));
}
DI void ldsm_x2(uint32_t* r, uint32_t a) {
    asm volatile("ldmatrix.sync.aligned.m8n8.x2.shared.b16 {%0,%1}, [%2];"
                 : "=r"(r[0]), "=r"(r[1]) : "r"(a));
}
DI void mma_fp8(float* d, const uint32_t* a, const uint32_t* b) {
    asm volatile(
        "mma.sync.aligned.m16n8k32.row.col.f32.e4m3.e4m3.f32 "
        "{%0,%1,%2,%3}, {%4,%5,%6,%7}, {%8,%9}, {%0,%1,%2,%3};"
        : "+f"(d[0]), "+f"(d[1]), "+f"(d[2]), "+f"(d[3])
        : "r"(a[0]), "r"(a[1]), "r"(a[2]), "r"(a[3]), "r"(b[0]), "r"(b[1]));
}

// ---------------- kernel 1: per-token dynamic quant of x ----------------
__global__ void __launch_bounds__(256) quant_x_kernel(const float* __restrict__ x) {
    int row = blockIdx.x;
    const float4* xr = reinterpret_cast<const float4*>(x + (size_t)row * K_DIM);
    float4 v[4];
    float amax = 0.f;
#pragma unroll
    for (int j = 0; j < 4; j++) {
        v[j] = xr[threadIdx.x + j * 256];
        amax = fmaxf(amax, fmaxf(fmaxf(fabsf(v[j].x), fabsf(v[j].y)),
                                 fmaxf(fabsf(v[j].z), fabsf(v[j].w))));
    }
#pragma unroll
    for (int o = 16; o; o >>= 1) amax = fmaxf(amax, __shfl_xor_sync(0xFFFFFFFFu, amax, o));
    __shared__ float wmax[8];
    __shared__ float s_scale;
    if ((threadIdx.x & 31) == 0) wmax[threadIdx.x >> 5] = amax;
    __syncthreads();
    if (threadIdx.x == 0) {
        float m = wmax[0];
#pragma unroll
        for (int i = 1; i < 8; i++) m = fmaxf(m, wmax[i]);
        float sc = fmaxf(__fdiv_rn(m, 448.0f), 1e-12f);   // exact RN div (fast-math-proof)
        g_xs[row] = sc;
        s_scale = sc;
    }
    __syncthreads();
    float sc = s_scale;
    uint32_t* outp = reinterpret_cast<uint32_t*>(g_xq + (size_t)row * K_DIM);
#pragma unroll
    for (int j = 0; j < 4; j++) {
        uint32_t p = (uint32_t)f2e4m3(__fdiv_rn(v[j].x, sc))
                   | ((uint32_t)f2e4m3(__fdiv_rn(v[j].y, sc)) << 8)
                   | ((uint32_t)f2e4m3(__fdiv_rn(v[j].z, sc)) << 16)
                   | ((uint32_t)f2e4m3(__fdiv_rn(v[j].w, sc)) << 24);
        outp[threadIdx.x + j * 256] = p;
    }
}

// ---------------- kernel 2: weight fp32 -> e4m3 repack (exact) ----------------
__global__ void __launch_bounds__(256) quant_w_kernel(const float* __restrict__ w) {
    size_t i = (size_t)blockIdx.x * blockDim.x + threadIdx.x;   // float4 index
    float4 v = reinterpret_cast<const float4*>(w)[i];
    uint32_t p = (uint32_t)f2e4m3(v.x)
               | ((uint32_t)f2e4m3(v.y) << 8)
               | ((uint32_t)f2e4m3(v.z) << 16)
               | ((uint32_t)f2e4m3(v.w) << 24);
    reinterpret_cast<uint32_t*>(g_wq)[i] = p;
}

// ---------------- shared tile loader (both paths) ----------------
DI void load_chunk(uint32_t sb, int s, int kc, int tid,
                   const unsigned char* gA, const unsigned char* gB) {
    uint32_t sa = sb + OFF_A + s * A_BYTES;
    uint32_t sbb = sb + OFF_B + s * B_BYTES;
    const unsigned char* pa = gA + (size_t)kc * KC;
    const unsigned char* pb = gB + (size_t)kc * KC;
#pragma unroll
    for (int i = 0; i < 6; i++) {            // (128+256)*8 / 512 = 6 x 16B per thread
        int idx = tid + i * NTHREADS;
        bool isA = idx < 1024;
        int loc = isA ? idx : idx - 1024;
        int row = loc >> 3;
        int c = loc & 7;
        uint32_t dst = (isA ? sa : sbb) + sw128((uint32_t)(row * 128 + c * 16));
        const unsigned char* src = (isA ? pa : pb) + (size_t)row * K_DIM + c * 16;
        cp16(dst, src);
    }
    cp_commit();
}

#if HAS_TC
// ---------------- tcgen05 helpers (only on "a" targets) ----------------
constexpr int TMEM_D   = 0;
constexpr int TMEM_SCA = 256;
constexpr int TMEM_SCB = 260;
constexpr int TMEM_COLS = 512;
constexpr uint32_t MMA_IDESC = (1u << 27) | (1u << 23) | ((NT / 8) << 17);
constexpr uint64_t SMEM_DESC_BASE_SW128 =
    (uint64_t(2) << 61) | (uint64_t(1) << 46) | (uint64_t(64) << 32) | (uint64_t(1) << 16);

DI uint32_t elect_one() {
    uint32_t r;
    asm volatile("{ .reg .pred p; elect.sync _|p, 0xFFFFFFFF; selp.b32 %0, 1, 0, p; }" : "=r"(r));
    return r;
}
#define TCGEN05_ALLOC(smem_addr, nCols) \
    asm volatile("tcgen05.alloc.cta_group::1.sync.aligned.shared::cta.b32 [%0], %1;" \
                 :: "r"((uint32_t)(smem_addr)), "r"((uint32_t)(nCols)) : "memory")
#define TCGEN05_DEALLOC(tmem_addr, nCols) \
    asm volatile("tcgen05.dealloc.cta_group::1.sync.aligned.b32 %0, %1;" :: "r"(tmem_addr), "r"(nCols))
#define TCGEN05_RELINQUISH() \
    asm volatile("tcgen05.relinquish_alloc_permit.cta_group::1.sync.aligned;")
#define TCGEN05_COMMIT(mbar) \
    asm volatile("tcgen05.commit.cta_group::1.mbarrier::arrive::one.shared::cluster.b64 [%0];" \
                 :: "r"((uint32_t)(mbar)) : "memory")
#define TCGEN05_WAIT_ST() asm volatile("tcgen05.wait::st.sync.aligned;" ::: "memory")
#define TCGEN05_WAIT_LD() asm volatile("tcgen05.wait::ld.sync.aligned;" ::: "memory")
#define TCGEN05_FENCE_BEFORE() asm volatile("tcgen05.fence::before_thread_sync;" ::: "memory")
#define TCGEN05_FENCE_AFTER()  asm volatile("tcgen05.fence::after_thread_sync;" ::: "memory")
#define TCGEN05_ST_32X32B_X1(tmem_addr, r0) \
    asm volatile("tcgen05.st.sync.aligned.32x32b.x1.b32 [%0], {%1};" :: "r"(tmem_addr), "r"(r0) : "memory")
#define TCGEN05_LD_32X32B_X32(r, tmem_addr) \
    asm volatile( \
        "tcgen05.ld.sync.aligned.32x32b.x32.b32 " \
        "{%0, %1, %2, %3, %4, %5, %6, %7, " \
        " %8, %9, %10, %11, %12, %13, %14, %15, " \
        " %16, %17, %18, %19, %20, %21, %22, %23, " \
        " %24, %25, %26, %27, %28, %29, %30, %31}, [%32];" \
        : "=r"((r)[0]),  "=r"((r)[1]),  "=r"((r)[2]),  "=r"((r)[3]), \
          "=r"((r)[4]),  "=r"((r)[5]),  "=r"((r)[6]),  "=r"((r)[7]), \
          "=r"((r)[8]),  "=r"((r)[9]),  "=r"((r)[10]), "=r"((r)[11]), \
          "=r"((r)[12]), "=r"((r)[13]), "=r"((r)[14]), "=r"((r)[15]), \
          "=r"((r)[16]), "=r"((r)[17]), "=r"((r)[18]), "=r"((r)[19]), \
          "=r"((r)[20]), "=r"((r)[21]), "=r"((r)[22]), "=r"((r)[23]), \
          "=r"((r)[24]), "=r"((r)[25]), "=r"((r)[26]), "=r"((r)[27]), \
          "=r"((r)[28]), "=r"((r)[29]), "=r"((r)[30]), "=r"((r)[31]) \
        : "r"(tmem_addr))

DI void mma_mxf8_ss(uint32_t d, uint64_t ad, uint64_t bd, uint32_t idesc,
                    uint32_t sfa, uint32_t sfb, bool acc) {
    uint32_t e = acc ? 1u : 0u;
    asm volatile(
        "{\n\t.reg .pred p;\n\tsetp.ne.u32 p, %6, 0;\n\t"
        "tcgen05.mma.cta_group::1.kind::mxf8f6f4.block_scale.scale_vec::1X "
        "[%0], %1, %2, %3, [%4], [%5], p;\n\t}"
        :: "r"(d), "l"(ad), "l"(bd), "r"(idesc), "r"(sfa), "r"(sfb), "r"(e)
        : "memory");
}
DI uint64_t make_desc(uint32_t base) {
    return SMEM_DESC_BASE_SW128 | ((uint64_t)(base >> 4) & 0x3FFF);
}
#endif  // HAS_TC

// ---------------- kernel 3: FP8 GEMM + fused dequant/bias ----------------
__global__ void __launch_bounds__(NTHREADS, 1) gemm_kernel(
    const float* __restrict__ wscale, const float* __restrict__ bias,
    float* __restrict__ out)
{
    extern __shared__ char smem[];
    uint32_t sb = smem_u32(smem);
    int tid = threadIdx.x;
    int m0 = blockIdx.x * MT;
    int n0 = blockIdx.y * NT;
    const unsigned char* gA = g_xq + (size_t)m0 * K_DIM;
    const unsigned char* gB = g_wq + (size_t)n0 * K_DIM;
    int lane = tid & 31, wid = tid >> 5;

#if HAS_TC
    // ============ tcgen05 path (selected when the sm_103a cubin is loaded) ============
    if (tid < 32) {
        TCGEN05_ALLOC(sb, TMEM_COLS);
        TCGEN05_RELINQUISH();
    }
    if (tid == 0) {
#pragma unroll
        for (int s = 0; s < STAGES; s++) mbar_init(sb + OFF_MBAR + 8 * s, 1);
    }
    __syncthreads();
    uint32_t tmem;
    asm volatile("ld.shared.b32 %0, [%1];" : "=r"(tmem) : "r"(sb));

    if (tid < 128) {      // ue8m0 1.0 scale factors, replicated across subpartitions
        uint32_t woff = ((uint32_t)(tid >> 5)) << 21;
#pragma unroll
        for (int c = 0; c < 4; c++) TCGEN05_ST_32X32B_X1(tmem + TMEM_SCA + c + woff, 0x7Fu);
#pragma unroll
        for (int c = 0; c < 8; c++) TCGEN05_ST_32X32B_X1(tmem + TMEM_SCB + c + woff, 0x7Fu);
        TCGEN05_WAIT_ST();
        TCGEN05_FENCE_BEFORE();
    }
    __syncthreads();
    if (tid < 32) TCGEN05_FENCE_AFTER();

#pragma unroll
    for (int i = 0; i < STAGES - 1; i++) load_chunk(sb, i, i, tid, gA, gB);

    int ph[STAGES];
#pragma unroll
    for (int s = 0; s < STAGES; s++) ph[s] = 0;

    for (int kc = 0; kc < NK; kc++) {
        int kl = kc + STAGES - 1;
        if (kl < NK) {
            int sl = kl % STAGES;
            if (kc >= 1) { mbar_wait(sb + OFF_MBAR + 8 * sl, (uint32_t)ph[sl]); ph[sl] ^= 1; }
            load_chunk(sb, sl, kl, tid, gA, gB);
            cp_wait_group<STAGES - 1>();
        } else {
            cp_wait_group<0>();
        }
        fence_async_smem();
        __syncthreads();

        int s = kc % STAGES;
        if (tid < 32) {
            if (elect_one()) {
                uint64_t ad = make_desc(sb + OFF_A + s * A_BYTES);
                uint64_t bd = make_desc(sb + OFF_B + s * B_BYTES);
#pragma unroll
                for (int k = 0; k < 4; k++)
                    mma_mxf8_ss(tmem + TMEM_D, ad + k * 2, bd + k * 2, MMA_IDESC,
                                tmem + TMEM_SCA, tmem + TMEM_SCB, (kc > 0) || (k > 0));
                TCGEN05_COMMIT(sb + OFF_MBAR + 8 * s);
            }
        }
    }

    int sL = (NK - 1) % STAGES;
    mbar_wait(sb + OFF_MBAR + 8 * sL, (uint32_t)ph[sL]);
    TCGEN05_FENCE_AFTER();

    {   // epilogue: 16 warps, subpartition = wid%4, column segment = wid/4
        int sub = wid & 3;
        int cseg = wid >> 2;
        int row = m0 + sub * 32 + lane;
        float xs = g_xs[row];
        float* orow = out + (size_t)row * N_DIM + n0 + cseg * 64;
#pragma unroll
        for (int cc = 0; cc < 2; cc++) {
            uint32_t d[32];
            TCGEN05_LD_32X32B_X32(d, tmem + TMEM_D + cseg * 64 + cc * 32);
            TCGEN05_WAIT_LD();
            int colg = n0 + cseg * 64 + cc * 32;
#pragma unroll
            for (int j = 0; j < 32; j += 4) {
                float4 r;
                r.x = __uint_as_float(d[j + 0]) * xs * __ldg(wscale + colg + j + 0) + __ldg(bias + colg + j + 0);
                r.y = __uint_as_float(d[j + 1]) * xs * __ldg(wscale + colg + j + 1) + __ldg(bias + colg + j + 1);
                r.z = __uint_as_float(d[j + 2]) * xs * __ldg(wscale + colg + j + 2) + __ldg(bias + colg + j + 2);
                r.w = __uint_as_float(d[j + 3]) * xs * __ldg(wscale + colg + j + 3) + __ldg(bias + colg + j + 3);
                *reinterpret_cast<float4*>(orow + cc * 32 + j) = r;
            }
        }
    }
    TCGEN05_FENCE_BEFORE();
    __syncthreads();
    if (tid == 0) {
#pragma unroll
        for (int s = 0; s < STAGES; s++) mbar_inval(sb + OFF_MBAR + 8 * s);
    }
    if (tid < 32) TCGEN05_DEALLOC(tmem, TMEM_COLS);

#else
    // ============ mma.sync fp8 path (legal at plain sm_103; slow fallback) ============
    // 16 warps in 2(M) x 8(N); warp tile 64x32; atoms m16n8k32.
    int wm = wid & 1;
    int wn = wid >> 1;

    // ldmatrix per-lane addressing (fp8 tiles viewed as b16 matrices).
    int rowA = wm * 64 + ((lane >> 3) & 1) * 8 + (lane & 7);
    int kA   = (lane >> 4) * 16;
    uint32_t xrA = (uint32_t)((rowA & 7) * 16);           // swizzle xor for this row
    int rowB = wn * 32 + (lane & 7);
    int kB   = ((lane >> 3) & 1) * 16;
    uint32_t xrB = (uint32_t)((rowB & 7) * 16);

    float d[4][4][4];
#pragma unroll
    for (int i = 0; i < 4; i++)
#pragma unroll
        for (int j = 0; j < 4; j++)
#pragma unroll
            for (int k = 0; k < 4; k++) d[i][j][k] = 0.f;

#pragma unroll
    for (int i = 0; i < STAGES - 1; i++) load_chunk(sb, i, i, tid, gA, gB);

    for (int kc = 0; kc < NK; kc++) {
        int kl = kc + STAGES - 1;
        if (kl < NK) {
            load_chunk(sb, kl % STAGES, kl, tid, gA, gB);
            cp_wait_group<STAGES - 1>();
        } else {
            cp_wait_group<0>();
        }
        __syncthreads();

        int s = kc % STAGES;
        uint32_t aBase = sb + OFF_A + s * A_BYTES + (uint32_t)rowA * 128;
        uint32_t bBase = sb + OFF_B + s * B_BYTES + (uint32_t)rowB * 128;
#pragma unroll
        for (int ks = 0; ks < 4; ks++) {
            uint32_t a[4][4], b[4][2];
            uint32_t colA = ((uint32_t)(kA + ks * 32)) ^ xrA;
            uint32_t colB = ((uint32_t)(kB + ks * 32)) ^ xrB;
#pragma unroll
            for (int am = 0; am < 4; am++) ldsm_x4(a[am], aBase + am * 2048 + colA);
#pragma unroll
            for (int bn = 0; bn < 4; bn++) ldsm_x2(b[bn], bBase + bn * 1024 + colB);
#pragma unroll
            for (int am = 0; am < 4; am++)
#pragma unroll
                for (int bn = 0; bn < 4; bn++) mma_fp8(d[am][bn], a[am], b[bn]);
        }
        __syncthreads();   // all warps done with stage s before it is overwritten
    }

    // epilogue: fused per-token * per-channel dequant + bias
    int g = lane >> 2, tig = lane & 3;
#pragma unroll
    for (int am = 0; am < 4; am++) {
        int r0 = m0 + wm * 64 + am * 16 + g;
        int r1 = r0 + 8;
        float xs0 = g_xs[r0], xs1 = g_xs[r1];
        float* p0 = out + (size_t)r0 * N_DIM;
        float* p1 = out + (size_t)r1 * N_DIM;
#pragma unroll
        for (int bn = 0; bn < 4; bn++) {
            int c = n0 + wn * 32 + bn * 8 + tig * 2;
            float2 ws = *reinterpret_cast<const float2*>(wscale + c);
            float2 bb = *reinterpret_cast<const float2*>(bias + c);
            float2 o0, o1;
            o0.x = d[am][bn][0] * xs0 * ws.x + bb.x;
            o0.y = d[am][bn][1] * xs0 * ws.y + bb.y;
            o1.x = d[am][bn][2] * xs1 * ws.x + bb.x;
            o1.y = d[am][bn][3] * xs1 * ws.y + bb.y;
            *reinterpret_cast<float2*>(p0 + c) = o0;
            *reinterpret_cast<float2*>(p1 + c) = o1;
        }
    }
#endif
}

// ---------------- launch ----------------
extern "C" void kernel_launch(void* const* d_in, const int* in_sizes, int n_in,
                              void* d_out, int out_size) {
    const float* x  = (const float*)d_in[0];
    const float* w  = (const float*)d_in[1];
    const float* ws = (const float*)d_in[2];
    const float* b  = (const float*)d_in[3];
    float* out = (float*)d_out;

    quant_x_kernel<<<M_DIM, 256>>>(x);
    quant_w_kernel<<<(unsigned)(((size_t)N_DIM * K_DIM / 4) / 256), 256>>>(w);

    cudaFuncSetAttribute(gemm_kernel, cudaFuncAttributeMaxDynamicSharedMemorySize, SMEM_BYTES);
    dim3 grid(M_DIM / MT, N_DIM / NT);   // (32, 64)
    gemm_kernel<<<grid, NTHREADS, SMEM_BYTES>>>(ws, b, out);
}

// round 17
// speedup vs baseline: 3.5013x; 1.1655x over previous
#include <cuda_runtime.h>
#include <cuda_fp8.h>
#include <stdint.h>

#define DI __device__ __forceinline__

// tcgen05 only exists on arch-specific ("a") targets.
#if defined(__CUDA_ARCH_FEAT_SM103_ALL) || defined(__CUDA_ARCH_FEAT_SM100_ALL)
#define HAS_TC 1
#else
#define HAS_TC 0
#endif

// ---------------- problem constants ----------------
constexpr int M_DIM = 4096;
constexpr int K_DIM = 4096;
constexpr int N_DIM = 16384;

// ---------------- GEMM tiling ----------------
constexpr int MT = 256;          // CTA M tile (two 128-row MMA sub-tiles)
constexpr int NT = 256;          // CTA N tile
constexpr int KC = 128;          // K bytes per chunk
constexpr int STAGES = 3;
constexpr int NK = K_DIM / KC;   // 32 chunks
constexpr int NTHREADS = 512;    // 16 warps

constexpr int A_BYTES = MT * KC;                      // 32768 (both halves)
constexpr int B_BYTES = NT * KC;                      // 32768
constexpr int OFF_MBAR = 16;
constexpr int OFF_A = 1024;
constexpr int OFF_B = OFF_A + STAGES * A_BYTES;       // 99328
constexpr int SMEM_BYTES = OFF_B + STAGES * B_BYTES;  // 197632

// ---------------- device scratch (allocation is forbidden) ----------------
__device__ unsigned char g_xq[(size_t)M_DIM * K_DIM];   // 16 MB fp8 activations
__device__ float         g_xs[M_DIM];                   // per-token scales
__device__ unsigned char g_wq[(size_t)N_DIM * K_DIM];   // 64 MB fp8 weights

// ---------------- generic PTX helpers (sm_90-safe) ----------------
DI uint32_t smem_u32(const void* p) {
    uint32_t a;
    asm("{ .reg .u64 t; cvta.to.shared.u64 t, %1; cvt.u32.u64 %0, t; }" : "=r"(a) : "l"(p));
    return a;
}
DI void mbar_init(uint32_t a, uint32_t cnt) {
    asm volatile("mbarrier.init.shared.b64 [%0], %1;" :: "r"(a), "r"(cnt) : "memory");
}
DI void mbar_inval(uint32_t a) {
    asm volatile("mbarrier.inval.shared.b64 [%0];" :: "r"(a) : "memory");
}
DI void mbar_wait(uint32_t a, uint32_t parity) {
    asm volatile(
        "{\n\t.reg .pred P;\n\t"
        "WLOOP_%=:\n\t"
        "mbarrier.try_wait.parity.acquire.cta.shared::cta.b64 P, [%0], %1, 0x989680;\n\t"
        "@P bra.uni WDONE_%=;\n\t"
        "bra.uni WLOOP_%=;\n\t"
        "WDONE_%=:\n\t}"
        :: "r"(a), "r"(parity) : "memory");
}
template <int N> DI void cp_wait_group() {
    asm volatile("cp.async.wait_group %0;" :: "n"(N) : "memory");
}
DI void cp_commit() { asm volatile("cp.async.commit_group;" ::: "memory"); }
DI void cp16(uint32_t dst, const void* src) {
    asm volatile("cp.async.cg.shared.global [%0], [%1], 16;" :: "r"(dst), "l"(src) : "memory");
}
DI void fence_async_smem() { asm volatile("fence.proxy.async.shared::cta;" ::: "memory"); }

DI uint32_t sw128(uint32_t off) { return off ^ ((off >> 3) & 0x70); }
DI uint8_t f2e4m3(float v) { return (uint8_t)__nv_cvt_float_to_fp8(v, __NV_SATFINITE, __NV_E4M3); }

// ldmatrix (b16 view of fp8 tiles gives exactly the fp8 m16n8k32 fragments)
DI void ldsm_x4(uint32_t* r, uint32_t a) {
    asm volatile("ldmatrix.sync.aligned.m8n8.x4.shared.b16 {%0,%1,%2,%3}, [%4];"
                 : "=r"(r[0]), "=r"(r[1]), "=r"(r[2]), "=r"(r[3]) : "r"(a));
}
DI void ldsm_x2(uint32_t* r, uint32_t a) {
    asm volatile("ldmatrix.sync.aligned.m8n8.x2.shared.b16 {%0,%1}, [%2];"
                 : "=r"(r[0]), "=r"(r[1]) : "r"(a));
}
DI void mma_fp8(float* d, const uint32_t* a, const uint32_t* b) {
    asm volatile(
        "mma.sync.aligned.m16n8k32.row.col.f32.e4m3.e4m3.f32 "
        "{%0,%1,%2,%3}, {%4,%5,%6,%7}, {%8,%9}, {%0,%1,%2,%3};"
        : "+f"(d[0]), "+f"(d[1]), "+f"(d[2]), "+f"(d[3])
        : "r"(a[0]), "r"(a[1]), "r"(a[2]), "r"(a[3]), "r"(b[0]), "r"(b[1]));
}

// ---------------- kernel 1: per-token dynamic quant of x ----------------
__global__ void __launch_bounds__(256) quant_x_kernel(const float* __restrict__ x) {
    int row = blockIdx.x;
    const float4* xr = reinterpret_cast<const float4*>(x + (size_t)row * K_DIM);
    float4 v[4];
    float amax = 0.f;
#pragma unroll
    for (int j = 0; j < 4; j++) {
        v[j] = xr[threadIdx.x + j * 256];
        amax = fmaxf(amax, fmaxf(fmaxf(fabsf(v[j].x), fabsf(v[j].y)),
                                 fmaxf(fabsf(v[j].z), fabsf(v[j].w))));
    }
#pragma unroll
    for (int o = 16; o; o >>= 1) amax = fmaxf(amax, __shfl_xor_sync(0xFFFFFFFFu, amax, o));
    __shared__ float wmax[8];
    __shared__ float s_scale;
    if ((threadIdx.x & 31) == 0) wmax[threadIdx.x >> 5] = amax;
    __syncthreads();
    if (threadIdx.x == 0) {
        float m = wmax[0];
#pragma unroll
        for (int i = 1; i < 8; i++) m = fmaxf(m, wmax[i]);
        float sc = fmaxf(__fdiv_rn(m, 448.0f), 1e-12f);
        g_xs[row] = sc;
        s_scale = sc;
    }
    __syncthreads();
    float sc = s_scale;
    uint32_t* outp = reinterpret_cast<uint32_t*>(g_xq + (size_t)row * K_DIM);
#pragma unroll
    for (int j = 0; j < 4; j++) {
        uint32_t p = (uint32_t)f2e4m3(__fdiv_rn(v[j].x, sc))
                   | ((uint32_t)f2e4m3(__fdiv_rn(v[j].y, sc)) << 8)
                   | ((uint32_t)f2e4m3(__fdiv_rn(v[j].z, sc)) << 16)
                   | ((uint32_t)f2e4m3(__fdiv_rn(v[j].w, sc)) << 24);
        outp[threadIdx.x + j * 256] = p;
    }
}

// ---------------- kernel 2: weight fp32 -> e4m3 repack (exact) ----------------
__global__ void __launch_bounds__(256) quant_w_kernel(const float* __restrict__ w) {
    size_t i = (size_t)blockIdx.x * blockDim.x + threadIdx.x;   // float4 index
    float4 v = reinterpret_cast<const float4*>(w)[i];
    uint32_t p = (uint32_t)f2e4m3(v.x)
               | ((uint32_t)f2e4m3(v.y) << 8)
               | ((uint32_t)f2e4m3(v.z) << 16)
               | ((uint32_t)f2e4m3(v.w) << 24);
    reinterpret_cast<uint32_t*>(g_wq)[i] = p;
}

// ---------------- shared tile loader (both paths) ----------------
// Per chunk: A 256 rows + B 256 rows, 128B each, SW128-swizzled.
// 512 rows x 8 cols16 = 4096 slots / 512 threads = 8 per thread.
DI void load_chunk(uint32_t sb, int s, int kc, int tid,
                   const unsigned char* gA, const unsigned char* gB) {
    uint32_t sa = sb + OFF_A + s * A_BYTES;
    uint32_t sbb = sb + OFF_B + s * B_BYTES;
    const unsigned char* pa = gA + (size_t)kc * KC;
    const unsigned char* pb = gB + (size_t)kc * KC;
#pragma unroll
    for (int i = 0; i < 8; i++) {
        int idx = tid + i * NTHREADS;
        bool isA = idx < 2048;
        int loc = isA ? idx : idx - 2048;
        int row = loc >> 3;
        int c = loc & 7;
        uint32_t dst = (isA ? sa : sbb) + sw128((uint32_t)(row * 128 + c * 16));
        const unsigned char* src = (isA ? pa : pb) + (size_t)row * K_DIM + c * 16;
        cp16(dst, src);
    }
    cp_commit();
}

#if HAS_TC
// ---------------- tcgen05 helpers (only on "a" targets) ----------------
constexpr int TMEM_D0 = 0;      // 256 fp32 cols (rows m0..m0+127)
constexpr int TMEM_D1 = 256;    // 256 fp32 cols (rows m0+128..m0+255)
constexpr int TMEM_COLS = 512;
// kind::f8f6f4 idesc: dtype F32 (bit4), atype/btype E4M3 (=0), N/8 @17, M/16 @24
constexpr uint32_t MMA_IDESC = (1u << 4) | ((NT / 8) << 17) | ((128 / 16) << 24);
constexpr uint64_t SMEM_DESC_BASE_SW128 =
    (uint64_t(2) << 61) | (uint64_t(1) << 46) | (uint64_t(64) << 32) | (uint64_t(1) << 16);

DI uint32_t elect_one() {
    uint32_t r;
    asm volatile("{ .reg .pred p; elect.sync _|p, 0xFFFFFFFF; selp.b32 %0, 1, 0, p; }" : "=r"(r));
    return r;
}
#define TCGEN05_ALLOC(smem_addr, nCols) \
    asm volatile("tcgen05.alloc.cta_group::1.sync.aligned.shared::cta.b32 [%0], %1;" \
                 :: "r"((uint32_t)(smem_addr)), "r"((uint32_t)(nCols)) : "memory")
#define TCGEN05_DEALLOC(tmem_addr, nCols) \
    asm volatile("tcgen05.dealloc.cta_group::1.sync.aligned.b32 %0, %1;" :: "r"(tmem_addr), "r"(nCols))
#define TCGEN05_RELINQUISH() \
    asm volatile("tcgen05.relinquish_alloc_permit.cta_group::1.sync.aligned;")
#define TCGEN05_COMMIT(mbar) \
    asm volatile("tcgen05.commit.cta_group::1.mbarrier::arrive::one.shared::cluster.b64 [%0];" \
                 :: "r"((uint32_t)(mbar)) : "memory")
#define TCGEN05_WAIT_LD() asm volatile("tcgen05.wait::ld.sync.aligned;" ::: "memory")
#define TCGEN05_FENCE_BEFORE() asm volatile("tcgen05.fence::before_thread_sync;" ::: "memory")
#define TCGEN05_FENCE_AFTER()  asm volatile("tcgen05.fence::after_thread_sync;" ::: "memory")
#define TCGEN05_LD_32X32B_X32(r, tmem_addr) \
    asm volatile( \
        "tcgen05.ld.sync.aligned.32x32b.x32.b32 " \
        "{%0, %1, %2, %3, %4, %5, %6, %7, " \
        " %8, %9, %10, %11, %12, %13, %14, %15, " \
        " %16, %17, %18, %19, %20, %21, %22, %23, " \
        " %24, %25, %26, %27, %28, %29, %30, %31}, [%32];" \
        : "=r"((r)[0]),  "=r"((r)[1]),  "=r"((r)[2]),  "=r"((r)[3]), \
          "=r"((r)[4]),  "=r"((r)[5]),  "=r"((r)[6]),  "=r"((r)[7]), \
          "=r"((r)[8]),  "=r"((r)[9]),  "=r"((r)[10]), "=r"((r)[11]), \
          "=r"((r)[12]), "=r"((r)[13]), "=r"((r)[14]), "=r"((r)[15]), \
          "=r"((r)[16]), "=r"((r)[17]), "=r"((r)[18]), "=r"((r)[19]), \
          "=r"((r)[20]), "=r"((r)[21]), "=r"((r)[22]), "=r"((r)[23]), \
          "=r"((r)[24]), "=r"((r)[25]), "=r"((r)[26]), "=r"((r)[27]), \
          "=r"((r)[28]), "=r"((r)[29]), "=r"((r)[30]), "=r"((r)[31]) \
        : "r"(tmem_addr))

// plain FP8 MMA (no block scale), disable-output-lane = all zeros (same form as kind::f16)
DI void mma_f8_ss(uint32_t d, uint64_t ad, uint64_t bd, uint32_t idesc, bool acc) {
    uint32_t e = acc ? 1u : 0u;
    asm volatile(
        "{\n\t.reg .pred p;\n\tsetp.ne.u32 p, %5, 0;\n\t"
        "tcgen05.mma.cta_group::1.kind::f8f6f4 [%0], %1, %2, %3, {%4, %4, %4, %4}, p;\n\t}"
        :: "r"(d), "l"(ad), "l"(bd), "r"(idesc), "r"(0u), "r"(e)
        : "memory");
}
DI uint64_t make_desc(uint32_t base) {
    return SMEM_DESC_BASE_SW128 | ((uint64_t)(base >> 4) & 0x3FFF);
}
#endif  // HAS_TC

// ---------------- kernel 3: FP8 GEMM + fused dequant/bias ----------------
__global__ void __launch_bounds__(NTHREADS, 1) gemm_kernel(
    const float* __restrict__ wscale, const float* __restrict__ bias,
    float* __restrict__ out)
{
    extern __shared__ char smem[];
    uint32_t sb = smem_u32(smem);
    int tid = threadIdx.x;
    int m0 = blockIdx.x * MT;
    int n0 = blockIdx.y * NT;
    const unsigned char* gA = g_xq + (size_t)m0 * K_DIM;
    const unsigned char* gB = g_wq + (size_t)n0 * K_DIM;
    int lane = tid & 31, wid = tid >> 5;

#if HAS_TC
    // ============ tcgen05 path: 256x256 CTA tile, D0+D1 fill all 512 TMEM cols ============
    if (tid < 32) {
        TCGEN05_ALLOC(sb, TMEM_COLS);
        TCGEN05_RELINQUISH();
    }
    if (tid == 0) {
#pragma unroll
        for (int s = 0; s < STAGES; s++) mbar_init(sb + OFF_MBAR + 8 * s, 1);
    }
    __syncthreads();
    uint32_t tmem;
    asm volatile("ld.shared.b32 %0, [%1];" : "=r"(tmem) : "r"(sb));

#pragma unroll
    for (int i = 0; i < STAGES - 1; i++) load_chunk(sb, i, i, tid, gA, gB);

    int ph[STAGES];
#pragma unroll
    for (int s = 0; s < STAGES; s++) ph[s] = 0;

    for (int kc = 0; kc < NK; kc++) {
        int kl = kc + STAGES - 1;
        if (kl < NK) {
            int sl = kl % STAGES;      // == (kc-1) % STAGES for kc >= 1
            if (kc >= 1) { mbar_wait(sb + OFF_MBAR + 8 * sl, (uint32_t)ph[sl]); ph[sl] ^= 1; }
            load_chunk(sb, sl, kl, tid, gA, gB);
            cp_wait_group<STAGES - 1>();
        } else {
            cp_wait_group<0>();
        }
        fence_async_smem();
        __syncthreads();

        int s = kc % STAGES;
        if (tid < 32) {
            if (elect_one()) {
                uint64_t a0 = make_desc(sb + OFF_A + s * A_BYTES);          // rows 0..127
                uint64_t a1 = make_desc(sb + OFF_A + s * A_BYTES + 16384);  // rows 128..255
                uint64_t bd = make_desc(sb + OFF_B + s * B_BYTES);
                bool acc0 = (kc > 0);
#pragma unroll
                for (int k = 0; k < 4; k++) {
                    bool acc = acc0 || (k > 0);
                    mma_f8_ss(tmem + TMEM_D0, a0 + k * 2, bd + k * 2, MMA_IDESC, acc);
                    mma_f8_ss(tmem + TMEM_D1, a1 + k * 2, bd + k * 2, MMA_IDESC, acc);
                }
                TCGEN05_COMMIT(sb + OFF_MBAR + 8 * s);
            }
        }
    }

    int sL = (NK - 1) % STAGES;
    mbar_wait(sb + OFF_MBAR + 8 * sL, (uint32_t)ph[sL]);
    TCGEN05_FENCE_AFTER();

    {   // epilogue: 16 warps = 4 subpartitions x 4 column segments of 128
        int sub = wid & 3;            // TMEM subpartition (HW: warp reads rows sub*32..+31)
        int seg = wid >> 2;           // 0..3: segs 0-1 -> D0, segs 2-3 -> D1
        int tile = seg >> 1;
        int half = seg & 1;
        int row = m0 + tile * 128 + sub * 32 + lane;
        float xs = g_xs[row];
        uint32_t tbase = tmem + tile * 256 + half * 128;
        float* orow = out + (size_t)row * N_DIM + n0 + half * 128;
#pragma unroll
        for (int cc = 0; cc < 4; cc++) {
            uint32_t d[32];
            TCGEN05_LD_32X32B_X32(d, tbase + cc * 32);
            TCGEN05_WAIT_LD();
            int colg = n0 + half * 128 + cc * 32;
#pragma unroll
            for (int j = 0; j < 32; j += 4) {
                float4 r;
                r.x = __uint_as_float(d[j + 0]) * xs * __ldg(wscale + colg + j + 0) + __ldg(bias + colg + j + 0);
                r.y = __uint_as_float(d[j + 1]) * xs * __ldg(wscale + colg + j + 1) + __ldg(bias + colg + j + 1);
                r.z = __uint_as_float(d[j + 2]) * xs * __ldg(wscale + colg + j + 2) + __ldg(bias + colg + j + 2);
                r.w = __uint_as_float(d[j + 3]) * xs * __ldg(wscale + colg + j + 3) + __ldg(bias + colg + j + 3);
                *reinterpret_cast<float4*>(orow + cc * 32 + j) = r;
            }
        }
    }
    TCGEN05_FENCE_BEFORE();
    __syncthreads();
    if (tid == 0) {
#pragma unroll
        for (int s = 0; s < STAGES; s++) mbar_inval(sb + OFF_MBAR + 8 * s);
    }
    if (tid < 32) TCGEN05_DEALLOC(tmem, TMEM_COLS);

#else
    // ============ mma.sync fp8 fallback (plain sm_103 pass; not selected at runtime) ======
    // Loops the proven 128x256 pipeline over the two M-halves of the 256-row tile.
    int wm = wid & 1;
    int wn = wid >> 1;

    int rowA = wm * 64 + ((lane >> 3) & 1) * 8 + (lane & 7);
    int kA   = (lane >> 4) * 16;
    uint32_t xrA = (uint32_t)((rowA & 7) * 16);
    int rowB = wn * 32 + (lane & 7);
    int kB   = ((lane >> 3) & 1) * 16;
    uint32_t xrB = (uint32_t)((rowB & 7) * 16);

    for (int h = 0; h < 2; h++) {
        int m0h = m0 + h * 128;
        float d[4][4][4];
#pragma unroll
        for (int i = 0; i < 4; i++)
#pragma unroll
            for (int j = 0; j < 4; j++)
#pragma unroll
                for (int k = 0; k < 4; k++) d[i][j][k] = 0.f;

#pragma unroll
        for (int i = 0; i < STAGES - 1; i++) load_chunk(sb, i, i, tid, gA, gB);

        for (int kc = 0; kc < NK; kc++) {
            int kl = kc + STAGES - 1;
            if (kl < NK) {
                load_chunk(sb, kl % STAGES, kl, tid, gA, gB);
                cp_wait_group<STAGES - 1>();
            } else {
                cp_wait_group<0>();
            }
            __syncthreads();

            int s = kc % STAGES;
            uint32_t aBase = sb + OFF_A + s * A_BYTES + (uint32_t)(h * 16384) + (uint32_t)rowA * 128;
            uint32_t bBase = sb + OFF_B + s * B_BYTES + (uint32_t)rowB * 128;
#pragma unroll
            for (int ks = 0; ks < 4; ks++) {
                uint32_t a[4][4], b[4][2];
                uint32_t colA = ((uint32_t)(kA + ks * 32)) ^ xrA;
                uint32_t colB = ((uint32_t)(kB + ks * 32)) ^ xrB;
#pragma unroll
                for (int am = 0; am < 4; am++) ldsm_x4(a[am], aBase + am * 2048 + colA);
#pragma unroll
                for (int bn = 0; bn < 4; bn++) ldsm_x2(b[bn], bBase + bn * 1024 + colB);
#pragma unroll
                for (int am = 0; am < 4; am++)
#pragma unroll
                    for (int bn = 0; bn < 4; bn++) mma_fp8(d[am][bn], a[am], b[bn]);
            }
            __syncthreads();
        }

        int g = lane >> 2, tig = lane & 3;
#pragma unroll
        for (int am = 0; am < 4; am++) {
            int r0 = m0h + wm * 64 + am * 16 + g;
            int r1 = r0 + 8;
            float xs0 = g_xs[r0], xs1 = g_xs[r1];
            float* p0 = out + (size_t)r0 * N_DIM;
            float* p1 = out + (size_t)r1 * N_DIM;
#pragma unroll
            for (int bn = 0; bn < 4; bn++) {
                int c = n0 + wn * 32 + bn * 8 + tig * 2;
                float2 ws = *reinterpret_cast<const float2*>(wscale + c);
                float2 bb = *reinterpret_cast<const float2*>(bias + c);
                float2 o0, o1;
                o0.x = d[am][bn][0] * xs0 * ws.x + bb.x;
                o0.y = d[am][bn][1] * xs0 * ws.y + bb.y;
                o1.x = d[am][bn][2] * xs1 * ws.x + bb.x;
                o1.y = d[am][bn][3] * xs1 * ws.y + bb.y;
                *reinterpret_cast<float2*>(p0 + c) = o0;
                *reinterpret_cast<float2*>(p1 + c) = o1;
            }
        }
        __syncthreads();   // all smem reads done before next half reloads stages
    }
#endif
}

// ---------------- launch ----------------
extern "C" void kernel_launch(void* const* d_in, const int* in_sizes, int n_in,
                              void* d_out, int out_size) {
    const float* x  = (const float*)d_in[0];
    const float* w  = (const float*)d_in[1];
    const float* ws = (const float*)d_in[2];
    const float* b  = (const float*)d_in[3];
    float* out = (float*)d_out;

    quant_x_kernel<<<M_DIM, 256>>>(x);
    quant_w_kernel<<<(unsigned)(((size_t)N_DIM * K_DIM / 4) / 256), 256>>>(w);

    cudaFuncSetAttribute(gemm_kernel, cudaFuncAttributeMaxDynamicSharedMemorySize, SMEM_BYTES);
    dim3 grid(M_DIM / MT, N_DIM / NT);   // (16, 64); x-fastest => B-tile reuse in L2
    gemm_kernel<<<grid, NTHREADS, SMEM_BYTES>>>(ws, b, out);
}